// round 1
// baseline (speedup 1.0000x reference)
#include <cuda_runtime.h>
#include <cstddef>

// Problem constants (fixed shapes for this problem)
#define NB 8    // batch
#define CC 8    // channels
#define TT 600  // time frames
#define FF 513  // freq bins
#define TS 10   // T-split chunks
#define TCH (TT / TS)       // 60 frames per chunk
#define NPAIR 28            // C*(C-1)/2 off-diagonal pairs
#define NACC 72             // 8 diag + 28 re + 28 im

__device__ float g_part[(size_t)TS * NB * NACC * FF];   // ~11.3 MB partial covariances
__device__ float g_w[(size_t)NB * CC * 2 * FF];         // conj(w), [n][c][re/im][f]

__device__ __forceinline__ int pair_idx(int c, int e) { // c < e
    return c * 7 - (c * (c - 1)) / 2 + (e - c - 1);
}

// ---------------------------------------------------------------------------
// Kernel 1: partial spatial covariance of target, Hermitian storage.
// grid: (ceil(F/128), N, TS), block: 128. Thread owns one f.
// ---------------------------------------------------------------------------
__global__ void __launch_bounds__(128) cov_kernel(const float* __restrict__ x) {
    int f = blockIdx.x * 128 + threadIdx.x;
    int n = blockIdx.y;
    int z = blockIdx.z;
    if (f >= FF) return;

    float diag[CC];
    float ore[NPAIR], oim[NPAIR];
#pragma unroll
    for (int c = 0; c < CC; ++c) diag[c] = 0.f;
#pragma unroll
    for (int k = 0; k < NPAIR; ++k) { ore[k] = 0.f; oim[k] = 0.f; }

    const size_t chanStride = (size_t)TT * FF;
    const float* xr = x + (size_t)(n * 2 + 0) * CC * chanStride + f;
    const float* xi = x + (size_t)(n * 2 + 1) * CC * chanStride + f;

    int t0 = z * TCH;
#pragma unroll 2
    for (int t = t0; t < t0 + TCH; ++t) {
        float a[CC], b[CC];
        size_t toff = (size_t)t * FF;
#pragma unroll
        for (int c = 0; c < CC; ++c) {
            a[c] = xr[(size_t)c * chanStride + toff];
            b[c] = xi[(size_t)c * chanStride + toff];
        }
#pragma unroll
        for (int c = 0; c < CC; ++c) diag[c] += a[c] * a[c] + b[c] * b[c];
        int k = 0;
#pragma unroll
        for (int c = 0; c < CC; ++c) {
#pragma unroll
            for (int e = c + 1; e < CC; ++e, ++k) {
                // phi[c][e] += x[c] * conj(x[e])
                ore[k] += a[c] * a[e] + b[c] * b[e];
                oim[k] += b[c] * a[e] - a[c] * b[e];
            }
        }
    }

    float* pb = g_part + ((size_t)(z * NB + n) * NACC) * FF + f;
#pragma unroll
    for (int c = 0; c < CC; ++c) pb[(size_t)c * FF] = diag[c];
#pragma unroll
    for (int k = 0; k < NPAIR; ++k) {
        pb[(size_t)(8 + k) * FF] = ore[k];
        pb[(size_t)(36 + k) * FF] = oim[k];
    }
}

// ---------------------------------------------------------------------------
// Kernel 2: reduce partials, add loading, solve MVDR weights, store conj(w).
// One thread per (n, f).
// ---------------------------------------------------------------------------
__global__ void __launch_bounds__(128) weight_kernel(const float* __restrict__ sv) {
    int id = blockIdx.x * 128 + threadIdx.x;
    if (id >= NB * FF) return;
    int n = id / FF;
    int f = id - n * FF;

    float acc[NACC];
#pragma unroll
    for (int k = 0; k < NACC; ++k) {
        float s = 0.f;
#pragma unroll
        for (int z = 0; z < TS; ++z)
            s += g_part[((size_t)(z * NB + n) * NACC + k) * FF + f];
        acc[k] = s;
    }

    const float invT = 1.0f / (float)TT;
    const float LOADC = 0.001f * 0.7071067811865475f;  // 0.001/sqrt(2)

    // steering vector d[f][c], layout [2, F, C, 1]
    float dr[CC], di[CC];
#pragma unroll
    for (int c = 0; c < CC; ++c) {
        dr[c] = sv[(size_t)(0 * FF + f) * CC + c];
        di[c] = sv[(size_t)(1 * FF + f) * CC + c];
    }

    // nume[c] = sum_e phi[c][e] * d[e], phi Hermitian + complex loading on diag
    float nr[CC], ni[CC];
#pragma unroll
    for (int c = 0; c < CC; ++c) {
        float pr = acc[c] * invT + LOADC;  // diag: real part + LOAD
        float pi = LOADC;                  // diag imag: LOAD
        float sr = pr * dr[c] - pi * di[c];
        float si = pr * di[c] + pi * dr[c];
#pragma unroll
        for (int e = 0; e < CC; ++e) {
            if (e == c) continue;
            float qr, qi;
            if (e > c) {
                int k = pair_idx(c, e);
                qr = acc[8 + k] * invT;
                qi = acc[36 + k] * invT;
            } else {
                int k = pair_idx(e, c);
                qr = acc[8 + k] * invT;
                qi = -acc[36 + k] * invT;
            }
            sr += qr * dr[e] - qi * di[e];
            si += qr * di[e] + qi * dr[e];
        }
        nr[c] = sr;
        ni[c] = si;
    }

    // deno = sum_c conj(d[c]) * nume[c]
    float der = 0.f, dei = 0.f;
#pragma unroll
    for (int c = 0; c < CC; ++c) {
        der += dr[c] * nr[c] + di[c] * ni[c];
        dei += dr[c] * ni[c] - di[c] * nr[c];
    }
    float inv = 1.0f / (der * der + dei * dei);

#pragma unroll
    for (int c = 0; c < CC; ++c) {
        float wr = (nr[c] * der + ni[c] * dei) * inv;
        float wi = (ni[c] * der - nr[c] * dei) * inv;
        // store conj(w)
        g_w[((size_t)(n * CC + c) * 2 + 0) * FF + f] = wr;
        g_w[((size_t)(n * CC + c) * 2 + 1) * FF + f] = -wi;
    }
}

// ---------------------------------------------------------------------------
// Kernel 3: beamform mixture with conj(w).
// grid: (ceil(F/128), T/TB, N), block 128. Thread owns one f, loops TB t's.
// ---------------------------------------------------------------------------
#define TB 8
__global__ void __launch_bounds__(128) bf_kernel(const float* __restrict__ y,
                                                 float* __restrict__ out) {
    int f = blockIdx.x * 128 + threadIdx.x;
    int n = blockIdx.z;
    int t0 = blockIdx.y * TB;
    if (f >= FF) return;

    float cwr[CC], cwi[CC];
#pragma unroll
    for (int c = 0; c < CC; ++c) {
        cwr[c] = g_w[((size_t)(n * CC + c) * 2 + 0) * FF + f];
        cwi[c] = g_w[((size_t)(n * CC + c) * 2 + 1) * FF + f];
    }

    const size_t chanStride = (size_t)TT * FF;
    const float* yr = y + (size_t)(n * 2 + 0) * CC * chanStride + f;
    const float* yi = y + (size_t)(n * 2 + 1) * CC * chanStride + f;
    float* outr = out + (size_t)(n * 2 + 0) * TT * FF + f;
    float* outi = out + (size_t)(n * 2 + 1) * TT * FF + f;

#pragma unroll
    for (int t = t0; t < t0 + TB; ++t) {
        size_t toff = (size_t)t * FF;
        float ar = 0.f, ai = 0.f;
#pragma unroll
        for (int c = 0; c < CC; ++c) {
            float a = yr[(size_t)c * chanStride + toff];
            float b = yi[(size_t)c * chanStride + toff];
            // conj(w) * y : (cwr + i cwi)(a + i b)
            ar += cwr[c] * a - cwi[c] * b;
            ai += cwr[c] * b + cwi[c] * a;
        }
        outr[toff] = ar;
        outi[toff] = ai;
    }
}

extern "C" void kernel_launch(void* const* d_in, const int* in_sizes, int n_in,
                              void* d_out, int out_size) {
    const float* mixture = (const float*)d_in[0];
    // d_in[1] = noise (unused by the reference computation)
    const float* target = (const float*)d_in[2];
    const float* sv = (const float*)d_in[3];
    float* out = (float*)d_out;

    dim3 gA((FF + 127) / 128, NB, TS);
    cov_kernel<<<gA, 128>>>(target);

    int nw = NB * FF;
    weight_kernel<<<(nw + 127) / 128, 128>>>(sv);

    dim3 gC((FF + 127) / 128, TT / TB, NB);
    bf_kernel<<<gC, 128>>>(mixture, out);
}